// round 1
// baseline (speedup 1.0000x reference)
#include <cuda_runtime.h>
#include <math.h>

#define B_      8
#define S_      2048
#define D_      320
#define NH_     5
#define HD_     64
#define FF_     864
#define NL_     6
#define NLOOPS_ 8
#define TOK_    (B_*S_)          // 16384
#define KSEL_   1638             // int(2048*0.8)
#define QKVW_   (3*D_)           // 960

// ---------------- scratch (device globals; no allocations allowed) ----------
static __device__ float g_X[TOK_*D_];                    // residual stream
static __device__ float g_H[TOK_*D_];                    // rmsnorm output
static __device__ float g_QKV[TOK_*QKVW_];               // qkv projections
static __device__ float g_AO[TOK_*D_];                   // attention output
static __device__ float g_G[TOK_*FF_];                   // mlp intermediate
static __device__ float g_RS[TOK_];                      // mask*prob per token
static __device__ float g_P[TOK_];                       // router probs

// ---------------- embedding + iter_emb --------------------------------------
__global__ void embed_kernel(const int* __restrict__ ids, const int* __restrict__ iter,
                             const float* __restrict__ emb, const float* __restrict__ iemb)
{
    int t = blockIdx.x;
    int id = ids[t];
    int it = iter[0];
    const float* e = emb + (size_t)id * D_;
    const float* a = (it >= 0 && it < NLOOPS_) ? (iemb + (size_t)it * D_) : nullptr;
    for (int d = threadIdx.x; d < D_; d += blockDim.x) {
        float v = e[d];
        if (a) v += a[d];
        g_X[(size_t)t * D_ + d] = v;
    }
}

// ---------------- rmsnorm: src is always g_X; dst = g_H or out ---------------
__global__ __launch_bounds__(128) void rmsnorm_kernel(const float* __restrict__ w,
                                                      float* __restrict__ outp)
{
    int t = blockIdx.x;
    const float* x = g_X + (size_t)t * D_;
    float* dst = outp ? (outp + (size_t)t * D_) : (g_H + (size_t)t * D_);
    float s = 0.f;
    for (int d = threadIdx.x; d < D_; d += 128) { float v = x[d]; s = fmaf(v, v, s); }
    #pragma unroll
    for (int o = 16; o > 0; o >>= 1) s += __shfl_xor_sync(0xffffffffu, s, o);
    __shared__ float red[4];
    if ((threadIdx.x & 31) == 0) red[threadIdx.x >> 5] = s;
    __syncthreads();
    s = red[0] + red[1] + red[2] + red[3];
    float inv = rsqrtf(s * (1.f / D_) + 1e-6f);
    for (int d = threadIdx.x; d < D_; d += 128) dst[d] = w[d] * x[d] * inv;
}

// ---------------- generic tiled SGEMM: C[M,N] (+)= A[M,K] @ Bw[N,K]^T --------
// asel: 0=g_H 1=g_AO 2=g_G ; csel: 0=g_QKV 1=g_X
// mode: 0 -> C = acc ; 1 -> C += rs*acc (rs = g_RS[m] if use_rs else 1)
__global__ __launch_bounds__(256) void gemm_kernel(
    int asel, const float* __restrict__ Bw, int csel,
    int M, int N, int K, int mode, int use_rs)
{
    const float* A = (asel == 0) ? g_H : (asel == 1) ? g_AO : g_G;
    float* C = (csel == 0) ? g_QKV : g_X;
    __shared__ float As[16 * 66];
    __shared__ float Bs[16 * 66];
    int tid = threadIdx.x;
    int tx4 = (tid & 15) * 4;
    int ty4 = (tid >> 4) * 4;
    int m0 = blockIdx.y * 64, n0 = blockIdx.x * 64;
    int lrow = tid >> 2;
    int lc = (tid & 3) * 4;
    float acc[4][4] = {};
    const float* Ap = A + (size_t)(m0 + lrow) * K + lc;
    bool bok = (n0 + lrow) < N;
    const float* Bp = Bw + (size_t)(bok ? (n0 + lrow) : 0) * K + lc;
    for (int k0 = 0; k0 < K; k0 += 16) {
        float4 av = *(const float4*)(Ap + k0);
        float4 bv = bok ? *(const float4*)(Bp + k0) : make_float4(0.f, 0.f, 0.f, 0.f);
        As[(lc + 0) * 66 + lrow] = av.x; As[(lc + 1) * 66 + lrow] = av.y;
        As[(lc + 2) * 66 + lrow] = av.z; As[(lc + 3) * 66 + lrow] = av.w;
        Bs[(lc + 0) * 66 + lrow] = bv.x; Bs[(lc + 1) * 66 + lrow] = bv.y;
        Bs[(lc + 2) * 66 + lrow] = bv.z; Bs[(lc + 3) * 66 + lrow] = bv.w;
        __syncthreads();
        #pragma unroll
        for (int k = 0; k < 16; k++) {
            float a0 = As[k*66+ty4+0], a1 = As[k*66+ty4+1], a2 = As[k*66+ty4+2], a3 = As[k*66+ty4+3];
            float b0 = Bs[k*66+tx4+0], b1 = Bs[k*66+tx4+1], b2 = Bs[k*66+tx4+2], b3 = Bs[k*66+tx4+3];
            acc[0][0]=fmaf(a0,b0,acc[0][0]); acc[0][1]=fmaf(a0,b1,acc[0][1]);
            acc[0][2]=fmaf(a0,b2,acc[0][2]); acc[0][3]=fmaf(a0,b3,acc[0][3]);
            acc[1][0]=fmaf(a1,b0,acc[1][0]); acc[1][1]=fmaf(a1,b1,acc[1][1]);
            acc[1][2]=fmaf(a1,b2,acc[1][2]); acc[1][3]=fmaf(a1,b3,acc[1][3]);
            acc[2][0]=fmaf(a2,b0,acc[2][0]); acc[2][1]=fmaf(a2,b1,acc[2][1]);
            acc[2][2]=fmaf(a2,b2,acc[2][2]); acc[2][3]=fmaf(a2,b3,acc[2][3]);
            acc[3][0]=fmaf(a3,b0,acc[3][0]); acc[3][1]=fmaf(a3,b1,acc[3][1]);
            acc[3][2]=fmaf(a3,b2,acc[3][2]); acc[3][3]=fmaf(a3,b3,acc[3][3]);
        }
        __syncthreads();
    }
    #pragma unroll
    for (int i = 0; i < 4; i++) {
        int m = m0 + ty4 + i;
        float rs = use_rs ? g_RS[m] : 1.f;
        #pragma unroll
        for (int j = 0; j < 4; j++) {
            int n = n0 + tx4 + j;
            if (n < N) {
                size_t idx = (size_t)m * N + n;
                float v = acc[i][j];
                if (mode == 0) C[idx] = v;
                else           C[idx] += rs * v;
            }
        }
    }
}

// ---------------- fused gate/up GEMM: g_G = silu(H@Gw^T) * (H@Uw^T) ----------
__global__ __launch_bounds__(256) void gateup_kernel(
    const float* __restrict__ Gw, const float* __restrict__ Uw)
{
    const int N = FF_, K = D_;
    __shared__ float As[16 * 66];
    __shared__ float Gs[16 * 66];
    __shared__ float Us[16 * 66];
    int tid = threadIdx.x;
    int tx4 = (tid & 15) * 4;
    int ty4 = (tid >> 4) * 4;
    int m0 = blockIdx.y * 64, n0 = blockIdx.x * 64;
    int lrow = tid >> 2;
    int lc = (tid & 3) * 4;
    float ag[4][4] = {}, au[4][4] = {};
    const float* Ap = g_H + (size_t)(m0 + lrow) * K + lc;
    bool bok = (n0 + lrow) < N;
    size_t boff = (size_t)(bok ? (n0 + lrow) : 0) * K + lc;
    for (int k0 = 0; k0 < K; k0 += 16) {
        float4 av = *(const float4*)(Ap + k0);
        float4 gv = bok ? *(const float4*)(Gw + boff + k0) : make_float4(0.f,0.f,0.f,0.f);
        float4 uv = bok ? *(const float4*)(Uw + boff + k0) : make_float4(0.f,0.f,0.f,0.f);
        As[(lc+0)*66+lrow]=av.x; As[(lc+1)*66+lrow]=av.y; As[(lc+2)*66+lrow]=av.z; As[(lc+3)*66+lrow]=av.w;
        Gs[(lc+0)*66+lrow]=gv.x; Gs[(lc+1)*66+lrow]=gv.y; Gs[(lc+2)*66+lrow]=gv.z; Gs[(lc+3)*66+lrow]=gv.w;
        Us[(lc+0)*66+lrow]=uv.x; Us[(lc+1)*66+lrow]=uv.y; Us[(lc+2)*66+lrow]=uv.z; Us[(lc+3)*66+lrow]=uv.w;
        __syncthreads();
        #pragma unroll
        for (int k = 0; k < 16; k++) {
            float a0 = As[k*66+ty4+0], a1 = As[k*66+ty4+1], a2 = As[k*66+ty4+2], a3 = As[k*66+ty4+3];
            float g0 = Gs[k*66+tx4+0], g1 = Gs[k*66+tx4+1], g2 = Gs[k*66+tx4+2], g3 = Gs[k*66+tx4+3];
            float u0 = Us[k*66+tx4+0], u1 = Us[k*66+tx4+1], u2 = Us[k*66+tx4+2], u3 = Us[k*66+tx4+3];
            ag[0][0]=fmaf(a0,g0,ag[0][0]); ag[0][1]=fmaf(a0,g1,ag[0][1]); ag[0][2]=fmaf(a0,g2,ag[0][2]); ag[0][3]=fmaf(a0,g3,ag[0][3]);
            ag[1][0]=fmaf(a1,g0,ag[1][0]); ag[1][1]=fmaf(a1,g1,ag[1][1]); ag[1][2]=fmaf(a1,g2,ag[1][2]); ag[1][3]=fmaf(a1,g3,ag[1][3]);
            ag[2][0]=fmaf(a2,g0,ag[2][0]); ag[2][1]=fmaf(a2,g1,ag[2][1]); ag[2][2]=fmaf(a2,g2,ag[2][2]); ag[2][3]=fmaf(a2,g3,ag[2][3]);
            ag[3][0]=fmaf(a3,g0,ag[3][0]); ag[3][1]=fmaf(a3,g1,ag[3][1]); ag[3][2]=fmaf(a3,g2,ag[3][2]); ag[3][3]=fmaf(a3,g3,ag[3][3]);
            au[0][0]=fmaf(a0,u0,au[0][0]); au[0][1]=fmaf(a0,u1,au[0][1]); au[0][2]=fmaf(a0,u2,au[0][2]); au[0][3]=fmaf(a0,u3,au[0][3]);
            au[1][0]=fmaf(a1,u0,au[1][0]); au[1][1]=fmaf(a1,u1,au[1][1]); au[1][2]=fmaf(a1,u2,au[1][2]); au[1][3]=fmaf(a1,u3,au[1][3]);
            au[2][0]=fmaf(a2,u0,au[2][0]); au[2][1]=fmaf(a2,u1,au[2][1]); au[2][2]=fmaf(a2,u2,au[2][2]); au[2][3]=fmaf(a2,u3,au[2][3]);
            au[3][0]=fmaf(a3,u0,au[3][0]); au[3][1]=fmaf(a3,u1,au[3][1]); au[3][2]=fmaf(a3,u2,au[3][2]); au[3][3]=fmaf(a3,u3,au[3][3]);
        }
        __syncthreads();
    }
    #pragma unroll
    for (int i = 0; i < 4; i++) {
        int m = m0 + ty4 + i;
        #pragma unroll
        for (int j = 0; j < 4; j++) {
            int n = n0 + tx4 + j;
            if (n < N) {
                float g = ag[i][j], u = au[i][j];
                g_G[(size_t)m * N + n] = (g / (1.f + expf(-g))) * u;
            }
        }
    }
}

// ---------------- RoPE in-place on q,k parts of g_QKV ------------------------
__global__ __launch_bounds__(160) void rope_kernel()
{
    int t = blockIdx.x;
    int s = t & (S_ - 1);
    int h = threadIdx.x >> 5;       // 0..4
    int i = threadIdx.x & 31;       // pair index 0..31
    float freq = expf(-((float)(2 * i) / (float)HD_) * 9.210340371976184f); // ln(10000)
    float ang = (float)s * freq;
    float sn, cs;
    sincosf(ang, &sn, &cs);
    float* qb = g_QKV + (size_t)t * QKVW_ + h * HD_;
    float q1 = qb[i], q2 = qb[i + 32];
    qb[i]      = q1 * cs - q2 * sn;
    qb[i + 32] = q2 * cs + q1 * sn;
    float* kb = qb + D_;
    float k1 = kb[i], k2 = kb[i + 32];
    kb[i]      = k1 * cs - k2 * sn;
    kb[i + 32] = k2 * cs + k1 * sn;
}

// ---------------- causal flash attention: 1 thread = 1 query -----------------
__global__ __launch_bounds__(128) void attn_kernel()
{
    int qb = blockIdx.x, h = blockIdx.y, b = blockIdx.z;
    int tid = threadIdx.x;
    int sq = qb * 128 + tid;
    const float4* qp = (const float4*)(g_QKV + (size_t)(b * S_ + sq) * QKVW_ + h * HD_);
    float q[64], o[64];
    #pragma unroll
    for (int i = 0; i < 16; i++) {
        float4 v = qp[i];
        q[4*i+0] = v.x * 0.125f; q[4*i+1] = v.y * 0.125f;
        q[4*i+2] = v.z * 0.125f; q[4*i+3] = v.w * 0.125f;
    }
    #pragma unroll
    for (int d = 0; d < 64; d++) o[d] = 0.f;
    float m = -1e30f, l = 0.f;
    __shared__ __align__(16) float Ks[64 * 64];
    __shared__ __align__(16) float Vs[64 * 64];
    int kend = qb * 128 + 128;
    for (int j0 = 0; j0 < kend; j0 += 64) {
        __syncthreads();
        #pragma unroll
        for (int it = 0; it < 8; it++) {
            int idx = it * 128 + tid;           // float4 index in 64x16
            int r = idx >> 4, c4 = idx & 15;
            const float4* kv = (const float4*)(g_QKV + (size_t)(b * S_ + j0 + r) * QKVW_ + h * HD_);
            ((float4*)Ks)[idx] = kv[80 + c4];   // +320 floats
            ((float4*)Vs)[idx] = kv[160 + c4];  // +640 floats
        }
        __syncthreads();
        if (j0 > sq) continue;
        int jm = sq - j0;
        int jend = (jm >= 63) ? 64 : (jm + 1);
        for (int j = 0; j < jend; j++) {
            const float4* kr = (const float4*)(Ks + j * 64);
            float s = 0.f;
            #pragma unroll
            for (int i = 0; i < 16; i++) {
                float4 kk = kr[i];
                s = fmaf(q[4*i+0], kk.x, s); s = fmaf(q[4*i+1], kk.y, s);
                s = fmaf(q[4*i+2], kk.z, s); s = fmaf(q[4*i+3], kk.w, s);
            }
            if (s > m) {
                float c = __expf(m - s);
                m = s; l *= c;
                #pragma unroll
                for (int d = 0; d < 64; d++) o[d] *= c;
            }
            float p = __expf(s - m);
            l += p;
            const float4* vr = (const float4*)(Vs + j * 64);
            #pragma unroll
            for (int i = 0; i < 16; i++) {
                float4 vv = vr[i];
                o[4*i+0] = fmaf(p, vv.x, o[4*i+0]); o[4*i+1] = fmaf(p, vv.y, o[4*i+1]);
                o[4*i+2] = fmaf(p, vv.z, o[4*i+2]); o[4*i+3] = fmaf(p, vv.w, o[4*i+3]);
            }
        }
    }
    float invl = 1.f / l;
    float4* op = (float4*)(g_AO + (size_t)(b * S_ + sq) * D_ + h * HD_);
    #pragma unroll
    for (int i = 0; i < 16; i++)
        op[i] = make_float4(o[4*i]*invl, o[4*i+1]*invl, o[4*i+2]*invl, o[4*i+3]*invl);
}

// ---------------- router: sigmoid(X . router_w) one warp per token -----------
__global__ __launch_bounds__(128) void router_kernel(const float* __restrict__ rw)
{
    int t = blockIdx.x * 4 + (threadIdx.x >> 5);
    int lane = threadIdx.x & 31;
    const float* x = g_X + (size_t)t * D_;
    float s = 0.f;
    for (int d = lane; d < D_; d += 32) s = fmaf(x[d], rw[d], s);
    #pragma unroll
    for (int o = 16; o > 0; o >>= 1) s += __shfl_xor_sync(0xffffffffu, s, o);
    if (lane == 0) g_P[t] = 1.f / (1.f + expf(-s));
}

// ---------------- exact stable top-k selection -> g_RS = mask * prob ---------
__global__ __launch_bounds__(1024) void select_kernel()
{
    __shared__ float p[S_];
    int b = blockIdx.x;
    for (int t = threadIdx.x; t < S_; t += 1024) p[t] = g_P[b * S_ + t];
    __syncthreads();
    for (int t = threadIdx.x; t < S_; t += 1024) {
        float pt = p[t];
        int rank = 0;
        for (int j = 0; j < S_; j++) {
            float pj = p[j];
            rank += (pj > pt) ? 1 : ((pj == pt && j < t) ? 1 : 0);
        }
        g_RS[b * S_ + t] = (rank < KSEL_) ? pt : 0.f;
    }
}

// ---------------- driver ------------------------------------------------------
extern "C" void kernel_launch(void* const* d_in, const int* in_sizes, int n_in,
                              void* d_out, int out_size)
{
    const int*   ids          = (const int*)d_in[0];
    const int*   iter         = (const int*)d_in[1];
    const float* emb          = (const float*)d_in[2];
    const float* iemb         = (const float*)d_in[3];
    const float* attn_norm_w  = (const float*)d_in[4];
    const float* Wqkv         = (const float*)d_in[5];
    const float* wo_w         = (const float*)d_in[6];
    const float* router_w     = (const float*)d_in[7];
    const float* mlp_norm_w   = (const float*)d_in[8];
    const float* gate_w       = (const float*)d_in[9];
    const float* up_w         = (const float*)d_in[10];
    const float* down_w       = (const float*)d_in[11];
    const float* final_norm_w = (const float*)d_in[12];
    float* out = (float*)d_out;

    embed_kernel<<<TOK_, 128>>>(ids, iter, emb, iemb);
    for (int l = 0; l < NL_; l++) {
        rmsnorm_kernel<<<TOK_, 128>>>(attn_norm_w + l * D_, nullptr);
        gemm_kernel<<<dim3(15, 256), 256>>>(0, Wqkv + (size_t)l * QKVW_ * D_, 0,
                                            TOK_, QKVW_, D_, 0, 0);
        rope_kernel<<<TOK_, 160>>>();
        attn_kernel<<<dim3(S_ / 128, NH_, B_), 128>>>();
        gemm_kernel<<<dim3(5, 256), 256>>>(1, wo_w + (size_t)l * D_ * D_, 1,
                                           TOK_, D_, D_, 1, 0);
        router_kernel<<<TOK_ / 4, 128>>>(router_w + l * D_);
        select_kernel<<<B_, 1024>>>();
        rmsnorm_kernel<<<TOK_, 128>>>(mlp_norm_w + l * D_, nullptr);
        gateup_kernel<<<dim3(14, 256), 256>>>(gate_w + (size_t)l * FF_ * D_,
                                              up_w + (size_t)l * FF_ * D_);
        gemm_kernel<<<dim3(5, 256), 256>>>(2, down_w + (size_t)l * D_ * FF_, 1,
                                           TOK_, D_, FF_, 1, 1);
    }
    rmsnorm_kernel<<<TOK_, 128>>>(final_norm_w, out);
}

// round 2
// speedup vs baseline: 1.4970x; 1.4970x over previous
#include <cuda_runtime.h>
#include <math.h>

#define B_      8
#define S_      2048
#define D_      320
#define NH_     5
#define HD_     64
#define FF_     864
#define NL_     6
#define NLOOPS_ 8
#define TOK_    (B_*S_)          // 16384
#define KSEL_   1638             // int(2048*0.8)
#define QKVW_   (3*D_)           // 960

typedef unsigned long long ull;

// ---------------- f32x2 packed helpers ---------------------------------------
__device__ __forceinline__ ull pk2(float x, float y) {
    ull r; asm("mov.b64 %0,{%1,%2};" : "=l"(r) : "f"(x), "f"(y)); return r;
}
__device__ __forceinline__ float2 upk(ull v) {
    float2 f; asm("mov.b64 {%0,%1},%2;" : "=f"(f.x), "=f"(f.y) : "l"(v)); return f;
}
__device__ __forceinline__ ull fma2(ull a, ull b, ull c) {
    ull d; asm("fma.rn.f32x2 %0,%1,%2,%3;" : "=l"(d) : "l"(a), "l"(b), "l"(c)); return d;
}

// ---------------- scratch (device globals; no allocations allowed) ----------
static __device__ float g_X[TOK_*D_];                    // residual stream
static __device__ float g_H[TOK_*D_];                    // rmsnorm output
static __device__ float g_QKV[TOK_*QKVW_];               // qkv projections
static __device__ float g_AO[TOK_*D_];                   // attention output
static __device__ float g_G[TOK_*FF_];                   // mlp intermediate
static __device__ float g_RS[TOK_];                      // mask*prob per token
static __device__ float g_P[TOK_];                       // router probs

// ---------------- embedding + iter_emb --------------------------------------
__global__ void embed_kernel(const int* __restrict__ ids, const int* __restrict__ iter,
                             const float* __restrict__ emb, const float* __restrict__ iemb)
{
    int t = blockIdx.x;
    int id = ids[t];
    int it = iter[0];
    const float* e = emb + (size_t)id * D_;
    const float* a = (it >= 0 && it < NLOOPS_) ? (iemb + (size_t)it * D_) : nullptr;
    for (int d = threadIdx.x; d < D_; d += blockDim.x) {
        float v = e[d];
        if (a) v += a[d];
        g_X[(size_t)t * D_ + d] = v;
    }
}

// ---------------- rmsnorm: src is always g_X; dst = g_H or out ---------------
__global__ __launch_bounds__(128) void rmsnorm_kernel(const float* __restrict__ w,
                                                      float* __restrict__ outp)
{
    int t = blockIdx.x;
    const float* x = g_X + (size_t)t * D_;
    float* dst = outp ? (outp + (size_t)t * D_) : (g_H + (size_t)t * D_);
    float s = 0.f;
    for (int d = threadIdx.x; d < D_; d += 128) { float v = x[d]; s = fmaf(v, v, s); }
    #pragma unroll
    for (int o = 16; o > 0; o >>= 1) s += __shfl_xor_sync(0xffffffffu, s, o);
    __shared__ float red[4];
    if ((threadIdx.x & 31) == 0) red[threadIdx.x >> 5] = s;
    __syncthreads();
    s = red[0] + red[1] + red[2] + red[3];
    float inv = rsqrtf(s * (1.f / D_) + 1e-6f);
    for (int d = threadIdx.x; d < D_; d += 128) dst[d] = w[d] * x[d] * inv;
}

// ============= f32x2 SGEMM: C[M,N] (+)= A[M,K] @ Bw[N,K]^T ==================
// 128x64 block tile, 4m x 8n micro-tile, 256 threads, BK=16.
// asel: 0=g_H 1=g_AO 2=g_G ; csel: 0=g_QKV 1=g_X
// mode: 0 -> C = acc ; 1 -> C += rs*acc (rs = g_RS[m] if use_rs else 1)
#define SA_ 132
#define SB_ 68
__global__ __launch_bounds__(256) void gemm_kernel(
    int asel, const float* __restrict__ Bw, int csel,
    int M, int N, int K, int mode, int use_rs)
{
    const float* A = (asel == 0) ? g_H : (asel == 1) ? g_AO : g_G;
    float* C = (csel == 0) ? g_QKV : g_X;
    __shared__ __align__(16) float As[16 * SA_];
    __shared__ __align__(16) float Bs[16 * SB_];
    int tid = threadIdx.x;
    int tx = tid & 7;          // n-group (8 cols)
    int ty = tid >> 3;         // m-group (4 rows)
    int m0 = blockIdx.y * 128, n0 = blockIdx.x * 64;

    int am = tid >> 1;                 // 0..127
    int ak = (tid & 1) * 8;            // 0 / 8
    const float* Ap = A + (size_t)(m0 + am) * K + ak;
    int bn = tid >> 2;                 // 0..63
    int bk = (tid & 3) * 4;
    bool bok = (n0 + bn) < N;
    const float* Bp = Bw + (size_t)(bok ? (n0 + bn) : 0) * K + bk;

    ull acc[4][4];
    #pragma unroll
    for (int j = 0; j < 4; j++)
        #pragma unroll
        for (int p = 0; p < 4; p++) acc[j][p] = 0ULL;

    for (int k0 = 0; k0 < K; k0 += 16) {
        float4 a0 = *(const float4*)(Ap + k0);
        float4 a1 = *(const float4*)(Ap + k0 + 4);
        float4 bv = bok ? *(const float4*)(Bp + k0) : make_float4(0.f, 0.f, 0.f, 0.f);
        __syncthreads();
        As[(ak+0)*SA_+am] = a0.x; As[(ak+1)*SA_+am] = a0.y;
        As[(ak+2)*SA_+am] = a0.z; As[(ak+3)*SA_+am] = a0.w;
        As[(ak+4)*SA_+am] = a1.x; As[(ak+5)*SA_+am] = a1.y;
        As[(ak+6)*SA_+am] = a1.z; As[(ak+7)*SA_+am] = a1.w;
        Bs[(bk+0)*SB_+bn] = bv.x; Bs[(bk+1)*SB_+bn] = bv.y;
        Bs[(bk+2)*SB_+bn] = bv.z; Bs[(bk+3)*SB_+bn] = bv.w;
        __syncthreads();
        #pragma unroll
        for (int k = 0; k < 16; k++) {
            float4 av = *(const float4*)(As + k * SA_ + ty * 4);
            ull ad0 = pk2(av.x, av.x), ad1 = pk2(av.y, av.y);
            ull ad2 = pk2(av.z, av.z), ad3 = pk2(av.w, av.w);
            const ulonglong2* bpp = (const ulonglong2*)(Bs + k * SB_ + tx * 8);
            ulonglong2 b0 = bpp[0], b1 = bpp[1];
            acc[0][0]=fma2(ad0,b0.x,acc[0][0]); acc[0][1]=fma2(ad0,b0.y,acc[0][1]);
            acc[0][2]=fma2(ad0,b1.x,acc[0][2]); acc[0][3]=fma2(ad0,b1.y,acc[0][3]);
            acc[1][0]=fma2(ad1,b0.x,acc[1][0]); acc[1][1]=fma2(ad1,b0.y,acc[1][1]);
            acc[1][2]=fma2(ad1,b1.x,acc[1][2]); acc[1][3]=fma2(ad1,b1.y,acc[1][3]);
            acc[2][0]=fma2(ad2,b0.x,acc[2][0]); acc[2][1]=fma2(ad2,b0.y,acc[2][1]);
            acc[2][2]=fma2(ad2,b1.x,acc[2][2]); acc[2][3]=fma2(ad2,b1.y,acc[2][3]);
            acc[3][0]=fma2(ad3,b0.x,acc[3][0]); acc[3][1]=fma2(ad3,b0.y,acc[3][1]);
            acc[3][2]=fma2(ad3,b1.x,acc[3][2]); acc[3][3]=fma2(ad3,b1.y,acc[3][3]);
        }
    }

    #pragma unroll
    for (int j = 0; j < 4; j++) {
        int m = m0 + ty * 4 + j;
        float rs = use_rs ? g_RS[m] : 1.f;
        int n = n0 + tx * 8;
        float2 v0 = upk(acc[j][0]), v1 = upk(acc[j][1]);
        float2 v2 = upk(acc[j][2]), v3 = upk(acc[j][3]);
        float* cp = C + (size_t)m * N + n;
        if (n + 4 <= N) {
            if (mode == 0) *(float4*)cp = make_float4(v0.x, v0.y, v1.x, v1.y);
            else { float4 o = *(const float4*)cp;
                   o.x += rs*v0.x; o.y += rs*v0.y; o.z += rs*v1.x; o.w += rs*v1.y;
                   *(float4*)cp = o; }
        }
        if (n + 8 <= N) {
            if (mode == 0) *(float4*)(cp+4) = make_float4(v2.x, v2.y, v3.x, v3.y);
            else { float4 o = *(const float4*)(cp+4);
                   o.x += rs*v2.x; o.y += rs*v2.y; o.z += rs*v3.x; o.w += rs*v3.y;
                   *(float4*)(cp+4) = o; }
        }
    }
}

// ======== fused gate/up f32x2 GEMM: g_G = silu(H@Gw^T) * (H@Uw^T) ===========
__global__ __launch_bounds__(256) void gateup_kernel(
    const float* __restrict__ Gw, const float* __restrict__ Uw)
{
    const int N = FF_, K = D_;
    __shared__ __align__(16) float As[16 * SA_];
    __shared__ __align__(16) float Gs[16 * SB_];
    __shared__ __align__(16) float Us[16 * SB_];
    int tid = threadIdx.x;
    int tx = tid & 7;
    int ty = tid >> 3;
    int m0 = blockIdx.y * 128, n0 = blockIdx.x * 64;

    int am = tid >> 1;
    int ak = (tid & 1) * 8;
    const float* Ap = g_H + (size_t)(m0 + am) * K + ak;
    int bn = tid >> 2;
    int bk = (tid & 3) * 4;
    bool bok = (n0 + bn) < N;
    size_t boff = (size_t)(bok ? (n0 + bn) : 0) * K + bk;

    ull ag[4][4], au[4][4];
    #pragma unroll
    for (int j = 0; j < 4; j++)
        #pragma unroll
        for (int p = 0; p < 4; p++) { ag[j][p] = 0ULL; au[j][p] = 0ULL; }

    for (int k0 = 0; k0 < K; k0 += 16) {
        float4 a0 = *(const float4*)(Ap + k0);
        float4 a1 = *(const float4*)(Ap + k0 + 4);
        float4 gv = bok ? *(const float4*)(Gw + boff + k0) : make_float4(0.f,0.f,0.f,0.f);
        float4 uv = bok ? *(const float4*)(Uw + boff + k0) : make_float4(0.f,0.f,0.f,0.f);
        __syncthreads();
        As[(ak+0)*SA_+am] = a0.x; As[(ak+1)*SA_+am] = a0.y;
        As[(ak+2)*SA_+am] = a0.z; As[(ak+3)*SA_+am] = a0.w;
        As[(ak+4)*SA_+am] = a1.x; As[(ak+5)*SA_+am] = a1.y;
        As[(ak+6)*SA_+am] = a1.z; As[(ak+7)*SA_+am] = a1.w;
        Gs[(bk+0)*SB_+bn] = gv.x; Gs[(bk+1)*SB_+bn] = gv.y;
        Gs[(bk+2)*SB_+bn] = gv.z; Gs[(bk+3)*SB_+bn] = gv.w;
        Us[(bk+0)*SB_+bn] = uv.x; Us[(bk+1)*SB_+bn] = uv.y;
        Us[(bk+2)*SB_+bn] = uv.z; Us[(bk+3)*SB_+bn] = uv.w;
        __syncthreads();
        #pragma unroll
        for (int k = 0; k < 16; k++) {
            float4 av = *(const float4*)(As + k * SA_ + ty * 4);
            ull ad0 = pk2(av.x, av.x), ad1 = pk2(av.y, av.y);
            ull ad2 = pk2(av.z, av.z), ad3 = pk2(av.w, av.w);
            const ulonglong2* gpp = (const ulonglong2*)(Gs + k * SB_ + tx * 8);
            ulonglong2 gb0 = gpp[0], gb1 = gpp[1];
            const ulonglong2* upp = (const ulonglong2*)(Us + k * SB_ + tx * 8);
            ulonglong2 ub0 = upp[0], ub1 = upp[1];
            ag[0][0]=fma2(ad0,gb0.x,ag[0][0]); ag[0][1]=fma2(ad0,gb0.y,ag[0][1]);
            ag[0][2]=fma2(ad0,gb1.x,ag[0][2]); ag[0][3]=fma2(ad0,gb1.y,ag[0][3]);
            ag[1][0]=fma2(ad1,gb0.x,ag[1][0]); ag[1][1]=fma2(ad1,gb0.y,ag[1][1]);
            ag[1][2]=fma2(ad1,gb1.x,ag[1][2]); ag[1][3]=fma2(ad1,gb1.y,ag[1][3]);
            ag[2][0]=fma2(ad2,gb0.x,ag[2][0]); ag[2][1]=fma2(ad2,gb0.y,ag[2][1]);
            ag[2][2]=fma2(ad2,gb1.x,ag[2][2]); ag[2][3]=fma2(ad2,gb1.y,ag[2][3]);
            ag[3][0]=fma2(ad3,gb0.x,ag[3][0]); ag[3][1]=fma2(ad3,gb0.y,ag[3][1]);
            ag[3][2]=fma2(ad3,gb1.x,ag[3][2]); ag[3][3]=fma2(ad3,gb1.y,ag[3][3]);
            au[0][0]=fma2(ad0,ub0.x,au[0][0]); au[0][1]=fma2(ad0,ub0.y,au[0][1]);
            au[0][2]=fma2(ad0,ub1.x,au[0][2]); au[0][3]=fma2(ad0,ub1.y,au[0][3]);
            au[1][0]=fma2(ad1,ub0.x,au[1][0]); au[1][1]=fma2(ad1,ub0.y,au[1][1]);
            au[1][2]=fma2(ad1,ub1.x,au[1][2]); au[1][3]=fma2(ad1,ub1.y,au[1][3]);
            au[2][0]=fma2(ad2,ub0.x,au[2][0]); au[2][1]=fma2(ad2,ub0.y,au[2][1]);
            au[2][2]=fma2(ad2,ub1.x,au[2][2]); au[2][3]=fma2(ad2,ub1.y,au[2][3]);
            au[3][0]=fma2(ad3,ub0.x,au[3][0]); au[3][1]=fma2(ad3,ub0.y,au[3][1]);
            au[3][2]=fma2(ad3,ub1.x,au[3][2]); au[3][3]=fma2(ad3,ub1.y,au[3][3]);
        }
    }

    #pragma unroll
    for (int j = 0; j < 4; j++) {
        int m = m0 + ty * 4 + j;
        int n = n0 + tx * 8;
        float* cp = g_G + (size_t)m * N + n;
        #pragma unroll
        for (int h = 0; h < 2; h++) {
            if (n + h * 4 + 4 <= N) {
                float2 ga = upk(ag[j][2*h]), gb = upk(ag[j][2*h+1]);
                float2 ua = upk(au[j][2*h]), ub = upk(au[j][2*h+1]);
                float4 o;
                o.x = (ga.x / (1.f + __expf(-ga.x))) * ua.x;
                o.y = (ga.y / (1.f + __expf(-ga.y))) * ua.y;
                o.z = (gb.x / (1.f + __expf(-gb.x))) * ub.x;
                o.w = (gb.y / (1.f + __expf(-gb.y))) * ub.y;
                *(float4*)(cp + h * 4) = o;
            }
        }
    }
}

// ---------------- RoPE in-place on q,k parts of g_QKV ------------------------
__global__ __launch_bounds__(160) void rope_kernel()
{
    int t = blockIdx.x;
    int s = t & (S_ - 1);
    int h = threadIdx.x >> 5;       // 0..4
    int i = threadIdx.x & 31;       // pair index 0..31
    float freq = expf(-((float)(2 * i) / (float)HD_) * 9.210340371976184f); // ln(10000)
    float ang = (float)s * freq;
    float sn, cs;
    sincosf(ang, &sn, &cs);
    float* qb = g_QKV + (size_t)t * QKVW_ + h * HD_;
    float q1 = qb[i], q2 = qb[i + 32];
    qb[i]      = q1 * cs - q2 * sn;
    qb[i + 32] = q2 * cs + q1 * sn;
    float* kb = qb + D_;
    float k1 = kb[i], k2 = kb[i + 32];
    kb[i]      = k1 * cs - k2 * sn;
    kb[i + 32] = k2 * cs + k1 * sn;
}

// ---------------- causal flash attention: 1 thread = 1 query -----------------
__global__ __launch_bounds__(128) void attn_kernel()
{
    int qb = blockIdx.x, h = blockIdx.y, b = blockIdx.z;
    int tid = threadIdx.x;
    int sq = qb * 128 + tid;
    const float4* qp = (const float4*)(g_QKV + (size_t)(b * S_ + sq) * QKVW_ + h * HD_);
    float q[64], o[64];
    #pragma unroll
    for (int i = 0; i < 16; i++) {
        float4 v = qp[i];
        q[4*i+0] = v.x * 0.125f; q[4*i+1] = v.y * 0.125f;
        q[4*i+2] = v.z * 0.125f; q[4*i+3] = v.w * 0.125f;
    }
    #pragma unroll
    for (int d = 0; d < 64; d++) o[d] = 0.f;
    float m = -1e30f, l = 0.f;
    __shared__ __align__(16) float Ks[64 * 64];
    __shared__ __align__(16) float Vs[64 * 64];
    int kend = qb * 128 + 128;
    for (int j0 = 0; j0 < kend; j0 += 64) {
        __syncthreads();
        #pragma unroll
        for (int it = 0; it < 8; it++) {
            int idx = it * 128 + tid;           // float4 index in 64x16
            int r = idx >> 4, c4 = idx & 15;
            const float4* kv = (const float4*)(g_QKV + (size_t)(b * S_ + j0 + r) * QKVW_ + h * HD_);
            ((float4*)Ks)[idx] = kv[80 + c4];   // +320 floats
            ((float4*)Vs)[idx] = kv[160 + c4];  // +640 floats
        }
        __syncthreads();
        if (j0 > sq) continue;
        int jm = sq - j0;
        int jend = (jm >= 63) ? 64 : (jm + 1);
        for (int j = 0; j < jend; j++) {
            const float4* kr = (const float4*)(Ks + j * 64);
            float s = 0.f;
            #pragma unroll
            for (int i = 0; i < 16; i++) {
                float4 kk = kr[i];
                s = fmaf(q[4*i+0], kk.x, s); s = fmaf(q[4*i+1], kk.y, s);
                s = fmaf(q[4*i+2], kk.z, s); s = fmaf(q[4*i+3], kk.w, s);
            }
            if (s > m) {
                float c = __expf(m - s);
                m = s; l *= c;
                #pragma unroll
                for (int d = 0; d < 64; d++) o[d] *= c;
            }
            float p = __expf(s - m);
            l += p;
            const float4* vr = (const float4*)(Vs + j * 64);
            #pragma unroll
            for (int i = 0; i < 16; i++) {
                float4 vv = vr[i];
                o[4*i+0] = fmaf(p, vv.x, o[4*i+0]); o[4*i+1] = fmaf(p, vv.y, o[4*i+1]);
                o[4*i+2] = fmaf(p, vv.z, o[4*i+2]); o[4*i+3] = fmaf(p, vv.w, o[4*i+3]);
            }
        }
    }
    float invl = 1.f / l;
    float4* op = (float4*)(g_AO + (size_t)(b * S_ + sq) * D_ + h * HD_);
    #pragma unroll
    for (int i = 0; i < 16; i++)
        op[i] = make_float4(o[4*i]*invl, o[4*i+1]*invl, o[4*i+2]*invl, o[4*i+3]*invl);
}

// ---------------- router: sigmoid(X . router_w) one warp per token -----------
__global__ __launch_bounds__(128) void router_kernel(const float* __restrict__ rw)
{
    int t = blockIdx.x * 4 + (threadIdx.x >> 5);
    int lane = threadIdx.x & 31;
    const float* x = g_X + (size_t)t * D_;
    float s = 0.f;
    for (int d = lane; d < D_; d += 32) s = fmaf(x[d], rw[d], s);
    #pragma unroll
    for (int o = 16; o > 0; o >>= 1) s += __shfl_xor_sync(0xffffffffu, s, o);
    if (lane == 0) g_P[t] = 1.f / (1.f + expf(-s));
}

// ---------------- exact stable top-k selection -> g_RS = mask * prob ---------
__global__ __launch_bounds__(1024) void select_kernel()
{
    __shared__ float p[S_];
    int b = blockIdx.x;
    for (int t = threadIdx.x; t < S_; t += 1024) p[t] = g_P[b * S_ + t];
    __syncthreads();
    for (int t = threadIdx.x; t < S_; t += 1024) {
        float pt = p[t];
        int rank = 0;
        for (int j = 0; j < S_; j++) {
            float pj = p[j];
            rank += (pj > pt) ? 1 : ((pj == pt && j < t) ? 1 : 0);
        }
        g_RS[b * S_ + t] = (rank < KSEL_) ? pt : 0.f;
    }
}

// ---------------- driver ------------------------------------------------------
extern "C" void kernel_launch(void* const* d_in, const int* in_sizes, int n_in,
                              void* d_out, int out_size)
{
    const int*   ids          = (const int*)d_in[0];
    const int*   iter         = (const int*)d_in[1];
    const float* emb          = (const float*)d_in[2];
    const float* iemb         = (const float*)d_in[3];
    const float* attn_norm_w  = (const float*)d_in[4];
    const float* Wqkv         = (const float*)d_in[5];
    const float* wo_w         = (const float*)d_in[6];
    const float* router_w     = (const float*)d_in[7];
    const float* mlp_norm_w   = (const float*)d_in[8];
    const float* gate_w       = (const float*)d_in[9];
    const float* up_w         = (const float*)d_in[10];
    const float* down_w       = (const float*)d_in[11];
    const float* final_norm_w = (const float*)d_in[12];
    float* out = (float*)d_out;

    embed_kernel<<<TOK_, 128>>>(ids, iter, emb, iemb);
    for (int l = 0; l < NL_; l++) {
        rmsnorm_kernel<<<TOK_, 128>>>(attn_norm_w + l * D_, nullptr);
        gemm_kernel<<<dim3(15, 128), 256>>>(0, Wqkv + (size_t)l * QKVW_ * D_, 0,
                                            TOK_, QKVW_, D_, 0, 0);
        rope_kernel<<<TOK_, 160>>>();
        attn_kernel<<<dim3(S_ / 128, NH_, B_), 128>>>();
        gemm_kernel<<<dim3(5, 128), 256>>>(1, wo_w + (size_t)l * D_ * D_, 1,
                                           TOK_, D_, D_, 1, 0);
        router_kernel<<<TOK_ / 4, 128>>>(router_w + l * D_);
        select_kernel<<<B_, 1024>>>();
        rmsnorm_kernel<<<TOK_, 128>>>(mlp_norm_w + l * D_, nullptr);
        gateup_kernel<<<dim3(14, 128), 256>>>(gate_w + (size_t)l * FF_ * D_,
                                              up_w + (size_t)l * FF_ * D_);
        gemm_kernel<<<dim3(5, 128), 256>>>(2, down_w + (size_t)l * D_ * FF_, 1,
                                           TOK_, D_, FF_, 1, 1);
    }
    rmsnorm_kernel<<<TOK_, 128>>>(final_norm_w, out);
}

// round 3
// speedup vs baseline: 1.6239x; 1.0847x over previous
#include <cuda_runtime.h>
#include <math.h>

#define B_      8
#define S_      2048
#define D_      320
#define NH_     5
#define HD_     64
#define FF_     864
#define NL_     6
#define NLOOPS_ 8
#define TOK_    (B_*S_)          // 16384
#define KSEL_   1638             // int(2048*0.8)
#define QKVW_   (3*D_)           // 960

typedef unsigned long long ull;

// ---------------- f32x2 packed helpers ---------------------------------------
__device__ __forceinline__ ull pk2(float x, float y) {
    ull r; asm("mov.b64 %0,{%1,%2};" : "=l"(r) : "f"(x), "f"(y)); return r;
}
__device__ __forceinline__ float2 upk(ull v) {
    float2 f; asm("mov.b64 {%0,%1},%2;" : "=f"(f.x), "=f"(f.y) : "l"(v)); return f;
}
__device__ __forceinline__ ull fma2(ull a, ull b, ull c) {
    ull d; asm("fma.rn.f32x2 %0,%1,%2,%3;" : "=l"(d) : "l"(a), "l"(b), "l"(c)); return d;
}
__device__ __forceinline__ ull mul2(ull a, ull b) {
    ull d; asm("mul.rn.f32x2 %0,%1,%2;" : "=l"(d) : "l"(a), "l"(b)); return d;
}

// ---------------- scratch (device globals; no allocations allowed) ----------
static __device__ float g_X[TOK_*D_];                    // residual stream
static __device__ float g_H[TOK_*D_];                    // rmsnorm output
static __device__ float g_QKV[TOK_*QKVW_];               // qkv projections
static __device__ float g_AO[TOK_*D_];                   // attention output
static __device__ float g_G[TOK_*FF_];                   // mlp intermediate
static __device__ float g_RS[TOK_];                      // mask*prob per token
static __device__ float g_P[TOK_];                       // router probs

// ---------------- embedding + iter_emb --------------------------------------
__global__ void embed_kernel(const int* __restrict__ ids, const int* __restrict__ iter,
                             const float* __restrict__ emb, const float* __restrict__ iemb)
{
    int t = blockIdx.x;
    int id = ids[t];
    int it = iter[0];
    const float* e = emb + (size_t)id * D_;
    const float* a = (it >= 0 && it < NLOOPS_) ? (iemb + (size_t)it * D_) : nullptr;
    for (int d = threadIdx.x; d < D_; d += blockDim.x) {
        float v = e[d];
        if (a) v += a[d];
        g_X[(size_t)t * D_ + d] = v;
    }
}

// ---------------- rmsnorm: src is always g_X; dst = g_H or out ---------------
__global__ __launch_bounds__(128) void rmsnorm_kernel(const float* __restrict__ w,
                                                      float* __restrict__ outp)
{
    int t = blockIdx.x;
    const float* x = g_X + (size_t)t * D_;
    float* dst = outp ? (outp + (size_t)t * D_) : (g_H + (size_t)t * D_);
    float s = 0.f;
    for (int d = threadIdx.x; d < D_; d += 128) { float v = x[d]; s = fmaf(v, v, s); }
    #pragma unroll
    for (int o = 16; o > 0; o >>= 1) s += __shfl_xor_sync(0xffffffffu, s, o);
    __shared__ float red[4];
    if ((threadIdx.x & 31) == 0) red[threadIdx.x >> 5] = s;
    __syncthreads();
    s = red[0] + red[1] + red[2] + red[3];
    float inv = rsqrtf(s * (1.f / D_) + 1e-6f);
    for (int d = threadIdx.x; d < D_; d += 128) dst[d] = w[d] * x[d] * inv;
}

// ============= pipelined f32x2 SGEMM: C[M,N] (+)= A[M,K] @ Bw[N,K]^T ========
// 128x64 block tile, 4m x 8n micro-tile, 256 threads, BK=16, reg double-buffer.
#define SA_ 132
#define SB_ 68
__global__ __launch_bounds__(256) void gemm_kernel(
    int asel, const float* __restrict__ Bw, int csel,
    int M, int N, int K, int mode, int use_rs)
{
    const float* A = (asel == 0) ? g_H : (asel == 1) ? g_AO : g_G;
    float* C = (csel == 0) ? g_QKV : g_X;
    __shared__ __align__(16) float As[16 * SA_];
    __shared__ __align__(16) float Bs[16 * SB_];
    int tid = threadIdx.x;
    int tx = tid & 7;          // n-group (8 cols)
    int ty = tid >> 3;         // m-group (4 rows)
    int m0 = blockIdx.y * 128, n0 = blockIdx.x * 64;

    int am = tid >> 1;                 // 0..127
    int ak = (tid & 1) * 8;            // 0 / 8
    const float* Ap = A + (size_t)(m0 + am) * K + ak;
    int bn = tid >> 2;                 // 0..63
    int bk = (tid & 3) * 4;
    bool bok = (n0 + bn) < N;
    const float* Bp = Bw + (size_t)(bok ? (n0 + bn) : 0) * K + bk;

    ull acc[4][4];
    #pragma unroll
    for (int j = 0; j < 4; j++)
        #pragma unroll
        for (int p = 0; p < 4; p++) acc[j][p] = 0ULL;

    // prologue: prefetch chunk 0
    float4 pa0 = *(const float4*)(Ap);
    float4 pa1 = *(const float4*)(Ap + 4);
    float4 pb  = bok ? *(const float4*)(Bp) : make_float4(0.f, 0.f, 0.f, 0.f);

    for (int k0 = 0; k0 < K; k0 += 16) {
        __syncthreads();
        As[(ak+0)*SA_+am] = pa0.x; As[(ak+1)*SA_+am] = pa0.y;
        As[(ak+2)*SA_+am] = pa0.z; As[(ak+3)*SA_+am] = pa0.w;
        As[(ak+4)*SA_+am] = pa1.x; As[(ak+5)*SA_+am] = pa1.y;
        As[(ak+6)*SA_+am] = pa1.z; As[(ak+7)*SA_+am] = pa1.w;
        Bs[(bk+0)*SB_+bn] = pb.x;  Bs[(bk+1)*SB_+bn] = pb.y;
        Bs[(bk+2)*SB_+bn] = pb.z;  Bs[(bk+3)*SB_+bn] = pb.w;
        __syncthreads();
        // prefetch next chunk during compute (clamped addr on last iter)
        int kn = (k0 + 16 < K) ? k0 + 16 : k0;
        pa0 = *(const float4*)(Ap + kn);
        pa1 = *(const float4*)(Ap + kn + 4);
        pb  = bok ? *(const float4*)(Bp + kn) : make_float4(0.f, 0.f, 0.f, 0.f);
        #pragma unroll
        for (int k = 0; k < 16; k++) {
            float4 av = *(const float4*)(As + k * SA_ + ty * 4);
            ull ad0 = pk2(av.x, av.x), ad1 = pk2(av.y, av.y);
            ull ad2 = pk2(av.z, av.z), ad3 = pk2(av.w, av.w);
            const ulonglong2* bpp = (const ulonglong2*)(Bs + k * SB_ + tx * 8);
            ulonglong2 b0 = bpp[0], b1 = bpp[1];
            acc[0][0]=fma2(ad0,b0.x,acc[0][0]); acc[0][1]=fma2(ad0,b0.y,acc[0][1]);
            acc[0][2]=fma2(ad0,b1.x,acc[0][2]); acc[0][3]=fma2(ad0,b1.y,acc[0][3]);
            acc[1][0]=fma2(ad1,b0.x,acc[1][0]); acc[1][1]=fma2(ad1,b0.y,acc[1][1]);
            acc[1][2]=fma2(ad1,b1.x,acc[1][2]); acc[1][3]=fma2(ad1,b1.y,acc[1][3]);
            acc[2][0]=fma2(ad2,b0.x,acc[2][0]); acc[2][1]=fma2(ad2,b0.y,acc[2][1]);
            acc[2][2]=fma2(ad2,b1.x,acc[2][2]); acc[2][3]=fma2(ad2,b1.y,acc[2][3]);
            acc[3][0]=fma2(ad3,b0.x,acc[3][0]); acc[3][1]=fma2(ad3,b0.y,acc[3][1]);
            acc[3][2]=fma2(ad3,b1.x,acc[3][2]); acc[3][3]=fma2(ad3,b1.y,acc[3][3]);
        }
    }

    #pragma unroll
    for (int j = 0; j < 4; j++) {
        int m = m0 + ty * 4 + j;
        float rs = use_rs ? g_RS[m] : 1.f;
        int n = n0 + tx * 8;
        float2 v0 = upk(acc[j][0]), v1 = upk(acc[j][1]);
        float2 v2 = upk(acc[j][2]), v3 = upk(acc[j][3]);
        float* cp = C + (size_t)m * N + n;
        if (n + 4 <= N) {
            if (mode == 0) *(float4*)cp = make_float4(v0.x, v0.y, v1.x, v1.y);
            else { float4 o = *(const float4*)cp;
                   o.x += rs*v0.x; o.y += rs*v0.y; o.z += rs*v1.x; o.w += rs*v1.y;
                   *(float4*)cp = o; }
        }
        if (n + 8 <= N) {
            if (mode == 0) *(float4*)(cp+4) = make_float4(v2.x, v2.y, v3.x, v3.y);
            else { float4 o = *(const float4*)(cp+4);
                   o.x += rs*v2.x; o.y += rs*v2.y; o.z += rs*v3.x; o.w += rs*v3.y;
                   *(float4*)(cp+4) = o; }
        }
    }
}

// ======== pipelined fused gate/up GEMM: g_G = silu(H@Gw^T) * (H@Uw^T) =======
__global__ __launch_bounds__(256) void gateup_kernel(
    const float* __restrict__ Gw, const float* __restrict__ Uw)
{
    const int N = FF_, K = D_;
    __shared__ __align__(16) float As[16 * SA_];
    __shared__ __align__(16) float Gs[16 * SB_];
    __shared__ __align__(16) float Us[16 * SB_];
    int tid = threadIdx.x;
    int tx = tid & 7;
    int ty = tid >> 3;
    int m0 = blockIdx.y * 128, n0 = blockIdx.x * 64;

    int am = tid >> 1;
    int ak = (tid & 1) * 8;
    const float* Ap = g_H + (size_t)(m0 + am) * K + ak;
    int bn = tid >> 2;
    int bk = (tid & 3) * 4;
    bool bok = (n0 + bn) < N;
    size_t boff = (size_t)(bok ? (n0 + bn) : 0) * K + bk;

    ull ag[4][4], au[4][4];
    #pragma unroll
    for (int j = 0; j < 4; j++)
        #pragma unroll
        for (int p = 0; p < 4; p++) { ag[j][p] = 0ULL; au[j][p] = 0ULL; }

    float4 pa0 = *(const float4*)(Ap);
    float4 pa1 = *(const float4*)(Ap + 4);
    float4 pg  = bok ? *(const float4*)(Gw + boff) : make_float4(0.f,0.f,0.f,0.f);
    float4 pu  = bok ? *(const float4*)(Uw + boff) : make_float4(0.f,0.f,0.f,0.f);

    for (int k0 = 0; k0 < K; k0 += 16) {
        __syncthreads();
        As[(ak+0)*SA_+am] = pa0.x; As[(ak+1)*SA_+am] = pa0.y;
        As[(ak+2)*SA_+am] = pa0.z; As[(ak+3)*SA_+am] = pa0.w;
        As[(ak+4)*SA_+am] = pa1.x; As[(ak+5)*SA_+am] = pa1.y;
        As[(ak+6)*SA_+am] = pa1.z; As[(ak+7)*SA_+am] = pa1.w;
        Gs[(bk+0)*SB_+bn] = pg.x;  Gs[(bk+1)*SB_+bn] = pg.y;
        Gs[(bk+2)*SB_+bn] = pg.z;  Gs[(bk+3)*SB_+bn] = pg.w;
        Us[(bk+0)*SB_+bn] = pu.x;  Us[(bk+1)*SB_+bn] = pu.y;
        Us[(bk+2)*SB_+bn] = pu.z;  Us[(bk+3)*SB_+bn] = pu.w;
        __syncthreads();
        int kn = (k0 + 16 < K) ? k0 + 16 : k0;
        pa0 = *(const float4*)(Ap + kn);
        pa1 = *(const float4*)(Ap + kn + 4);
        pg  = bok ? *(const float4*)(Gw + boff + kn) : make_float4(0.f,0.f,0.f,0.f);
        pu  = bok ? *(const float4*)(Uw + boff + kn) : make_float4(0.f,0.f,0.f,0.f);
        #pragma unroll
        for (int k = 0; k < 16; k++) {
            float4 av = *(const float4*)(As + k * SA_ + ty * 4);
            ull ad0 = pk2(av.x, av.x), ad1 = pk2(av.y, av.y);
            ull ad2 = pk2(av.z, av.z), ad3 = pk2(av.w, av.w);
            const ulonglong2* gpp = (const ulonglong2*)(Gs + k * SB_ + tx * 8);
            ulonglong2 gb0 = gpp[0], gb1 = gpp[1];
            const ulonglong2* upp = (const ulonglong2*)(Us + k * SB_ + tx * 8);
            ulonglong2 ub0 = upp[0], ub1 = upp[1];
            ag[0][0]=fma2(ad0,gb0.x,ag[0][0]); ag[0][1]=fma2(ad0,gb0.y,ag[0][1]);
            ag[0][2]=fma2(ad0,gb1.x,ag[0][2]); ag[0][3]=fma2(ad0,gb1.y,ag[0][3]);
            ag[1][0]=fma2(ad1,gb0.x,ag[1][0]); ag[1][1]=fma2(ad1,gb0.y,ag[1][1]);
            ag[1][2]=fma2(ad1,gb1.x,ag[1][2]); ag[1][3]=fma2(ad1,gb1.y,ag[1][3]);
            ag[2][0]=fma2(ad2,gb0.x,ag[2][0]); ag[2][1]=fma2(ad2,gb0.y,ag[2][1]);
            ag[2][2]=fma2(ad2,gb1.x,ag[2][2]); ag[2][3]=fma2(ad2,gb1.y,ag[2][3]);
            ag[3][0]=fma2(ad3,gb0.x,ag[3][0]); ag[3][1]=fma2(ad3,gb0.y,ag[3][1]);
            ag[3][2]=fma2(ad3,gb1.x,ag[3][2]); ag[3][3]=fma2(ad3,gb1.y,ag[3][3]);
            au[0][0]=fma2(ad0,ub0.x,au[0][0]); au[0][1]=fma2(ad0,ub0.y,au[0][1]);
            au[0][2]=fma2(ad0,ub1.x,au[0][2]); au[0][3]=fma2(ad0,ub1.y,au[0][3]);
            au[1][0]=fma2(ad1,ub0.x,au[1][0]); au[1][1]=fma2(ad1,ub0.y,au[1][1]);
            au[1][2]=fma2(ad1,ub1.x,au[1][2]); au[1][3]=fma2(ad1,ub1.y,au[1][3]);
            au[2][0]=fma2(ad2,ub0.x,au[2][0]); au[2][1]=fma2(ad2,ub0.y,au[2][1]);
            au[2][2]=fma2(ad2,ub1.x,au[2][2]); au[2][3]=fma2(ad2,ub1.y,au[2][3]);
            au[3][0]=fma2(ad3,ub0.x,au[3][0]); au[3][1]=fma2(ad3,ub0.y,au[3][1]);
            au[3][2]=fma2(ad3,ub1.x,au[3][2]); au[3][3]=fma2(ad3,ub1.y,au[3][3]);
        }
    }

    #pragma unroll
    for (int j = 0; j < 4; j++) {
        int m = m0 + ty * 4 + j;
        int n = n0 + tx * 8;
        float* cp = g_G + (size_t)m * N + n;
        #pragma unroll
        for (int h = 0; h < 2; h++) {
            if (n + h * 4 + 4 <= N) {
                float2 ga = upk(ag[j][2*h]), gb = upk(ag[j][2*h+1]);
                float2 ua = upk(au[j][2*h]), ub = upk(au[j][2*h+1]);
                float4 o;
                o.x = (ga.x / (1.f + __expf(-ga.x))) * ua.x;
                o.y = (ga.y / (1.f + __expf(-ga.y))) * ua.y;
                o.z = (gb.x / (1.f + __expf(-gb.x))) * ub.x;
                o.w = (gb.y / (1.f + __expf(-gb.y))) * ub.y;
                *(float4*)(cp + h * 4) = o;
            }
        }
    }
}

// ---------------- RoPE in-place on q,k parts of g_QKV ------------------------
__global__ __launch_bounds__(160) void rope_kernel()
{
    int t = blockIdx.x;
    int s = t & (S_ - 1);
    int h = threadIdx.x >> 5;       // 0..4
    int i = threadIdx.x & 31;       // pair index 0..31
    float freq = expf(-((float)(2 * i) / (float)HD_) * 9.210340371976184f); // ln(10000)
    float ang = (float)s * freq;
    float sn, cs;
    sincosf(ang, &sn, &cs);
    float* qb = g_QKV + (size_t)t * QKVW_ + h * HD_;
    float q1 = qb[i], q2 = qb[i + 32];
    qb[i]      = q1 * cs - q2 * sn;
    qb[i + 32] = q2 * cs + q1 * sn;
    float* kb = qb + D_;
    float k1 = kb[i], k2 = kb[i + 32];
    kb[i]      = k1 * cs - k2 * sn;
    kb[i + 32] = k2 * cs + k1 * sn;
}

// ---------------- causal flash attention, f32x2 math -------------------------
__global__ __launch_bounds__(128) void attn_kernel()
{
    int qb = blockIdx.x, h = blockIdx.y, b = blockIdx.z;
    int tid = threadIdx.x;
    int sq = qb * 128 + tid;
    const float4* qp = (const float4*)(g_QKV + (size_t)(b * S_ + sq) * QKVW_ + h * HD_);
    ull q2r[32], o2[32];
    #pragma unroll
    for (int i = 0; i < 16; i++) {
        float4 v = qp[i];
        q2r[2*i+0] = pk2(v.x * 0.125f, v.y * 0.125f);
        q2r[2*i+1] = pk2(v.z * 0.125f, v.w * 0.125f);
    }
    #pragma unroll
    for (int i = 0; i < 32; i++) o2[i] = 0ULL;
    float m = -1e30f, l = 0.f;
    __shared__ __align__(16) float Ks[64 * 64];
    __shared__ __align__(16) float Vs[64 * 64];
    int kend = qb * 128 + 128;
    for (int j0 = 0; j0 < kend; j0 += 64) {
        __syncthreads();
        #pragma unroll
        for (int it = 0; it < 8; it++) {
            int idx = it * 128 + tid;           // float4 index in 64x16
            int r = idx >> 4, c4 = idx & 15;
            const float4* kv = (const float4*)(g_QKV + (size_t)(b * S_ + j0 + r) * QKVW_ + h * HD_);
            ((float4*)Ks)[idx] = kv[80 + c4];   // +320 floats (K)
            ((float4*)Vs)[idx] = kv[160 + c4];  // +640 floats (V)
        }
        __syncthreads();
        if (j0 > sq) continue;
        int jm = sq - j0;
        int jend = (jm >= 63) ? 64 : (jm + 1);
        for (int j = 0; j < jend; j++) {
            const ulonglong2* kr = (const ulonglong2*)(Ks + j * 64);
            ull s2 = 0ULL;
            #pragma unroll
            for (int i = 0; i < 16; i++) {
                ulonglong2 kk = kr[i];
                s2 = fma2(q2r[2*i+0], kk.x, s2);
                s2 = fma2(q2r[2*i+1], kk.y, s2);
            }
            float2 sf = upk(s2);
            float s = sf.x + sf.y;
            if (s > m) {
                float c = __expf(m - s);
                m = s; l *= c;
                ull c2 = pk2(c, c);
                #pragma unroll
                for (int i = 0; i < 32; i++) o2[i] = mul2(o2[i], c2);
            }
            float p = __expf(s - m);
            l += p;
            ull p2 = pk2(p, p);
            const ulonglong2* vr = (const ulonglong2*)(Vs + j * 64);
            #pragma unroll
            for (int i = 0; i < 16; i++) {
                ulonglong2 vv = vr[i];
                o2[2*i+0] = fma2(p2, vv.x, o2[2*i+0]);
                o2[2*i+1] = fma2(p2, vv.y, o2[2*i+1]);
            }
        }
    }
    float invl = 1.f / l;
    float4* op = (float4*)(g_AO + (size_t)(b * S_ + sq) * D_ + h * HD_);
    #pragma unroll
    for (int i = 0; i < 16; i++) {
        float2 a = upk(o2[2*i]), c = upk(o2[2*i+1]);
        op[i] = make_float4(a.x * invl, a.y * invl, c.x * invl, c.y * invl);
    }
}

// ---------------- router: sigmoid(X . router_w) one warp per token -----------
__global__ __launch_bounds__(128) void router_kernel(const float* __restrict__ rw)
{
    int t = blockIdx.x * 4 + (threadIdx.x >> 5);
    int lane = threadIdx.x & 31;
    const float* x = g_X + (size_t)t * D_;
    float s = 0.f;
    for (int d = lane; d < D_; d += 32) s = fmaf(x[d], rw[d], s);
    #pragma unroll
    for (int o = 16; o > 0; o >>= 1) s += __shfl_xor_sync(0xffffffffu, s, o);
    if (lane == 0) g_P[t] = 1.f / (1.f + expf(-s));
}

// ---------------- exact stable top-k selection -> g_RS = mask * prob ---------
// grid (B_, 8), 256 threads; block handles 256 tokens of batch b.
__global__ __launch_bounds__(256) void select_kernel()
{
    __shared__ float p[S_];
    int b = blockIdx.x;
    for (int t = threadIdx.x; t < S_; t += 256) p[t] = g_P[b * S_ + t];
    __syncthreads();
    int t = blockIdx.y * 256 + threadIdx.x;
    float pt = p[t];
    int rank = 0;
    for (int j = 0; j < S_; j++) {
        float pj = p[j];
        rank += (pj > pt) ? 1 : ((pj == pt && j < t) ? 1 : 0);
    }
    g_RS[b * S_ + t] = (rank < KSEL_) ? pt : 0.f;
}

// ---------------- driver ------------------------------------------------------
extern "C" void kernel_launch(void* const* d_in, const int* in_sizes, int n_in,
                              void* d_out, int out_size)
{
    const int*   ids          = (const int*)d_in[0];
    const int*   iter         = (const int*)d_in[1];
    const float* emb          = (const float*)d_in[2];
    const float* iemb         = (const float*)d_in[3];
    const float* attn_norm_w  = (const float*)d_in[4];
    const float* Wqkv         = (const float*)d_in[5];
    const float* wo_w         = (const float*)d_in[6];
    const float* router_w     = (const float*)d_in[7];
    const float* mlp_norm_w   = (const float*)d_in[8];
    const float* gate_w       = (const float*)d_in[9];
    const float* up_w         = (const float*)d_in[10];
    const float* down_w       = (const float*)d_in[11];
    const float* final_norm_w = (const float*)d_in[12];
    float* out = (float*)d_out;

    embed_kernel<<<TOK_, 128>>>(ids, iter, emb, iemb);
    for (int l = 0; l < NL_; l++) {
        rmsnorm_kernel<<<TOK_, 128>>>(attn_norm_w + l * D_, nullptr);
        gemm_kernel<<<dim3(15, 128), 256>>>(0, Wqkv + (size_t)l * QKVW_ * D_, 0,
                                            TOK_, QKVW_, D_, 0, 0);
        rope_kernel<<<TOK_, 160>>>();
        attn_kernel<<<dim3(S_ / 128, NH_, B_), 128>>>();
        gemm_kernel<<<dim3(5, 128), 256>>>(1, wo_w + (size_t)l * D_ * D_, 1,
                                           TOK_, D_, D_, 1, 0);
        router_kernel<<<TOK_ / 4, 128>>>(router_w + l * D_);
        select_kernel<<<dim3(B_, 8), 256>>>();
        rmsnorm_kernel<<<TOK_, 128>>>(mlp_norm_w + l * D_, nullptr);
        gateup_kernel<<<dim3(14, 128), 256>>>(gate_w + (size_t)l * FF_ * D_,
                                              up_w + (size_t)l * FF_ * D_);
        gemm_kernel<<<dim3(5, 128), 256>>>(2, down_w + (size_t)l * D_ * FF_, 1,
                                           TOK_, D_, FF_, 1, 1);
    }
    rmsnorm_kernel<<<TOK_, 128>>>(final_norm_w, out);
}